// round 1
// baseline (speedup 1.0000x reference)
#include <cuda_runtime.h>
#include <cstdint>

// Tensor-train chain contraction, fp32, packed-f32x2 CUDA-core kernel.
//   v0[b,r]     = sum_i fc[i,r] * x[b,0,i]
//   step s:     v[b,r] <- sum_{l,i} v[b,l] * x[b,s+1,i] * mc[s,l,i,r]
//   out[b]      = sum_r v[b,r] * (sum_i lc[r,i] * x[b,127,i])
//
// Reformulated per step as v_new = w @ C_s with w[k=4l+i] = v[l]*x[i] (K=256, N=64).

#define BATCH   4096
#define LEN     128
#define FEATD   4
#define RANK    64
#define NSTEP   126
#define KDIM    256            // RANK*FEATD
#define TB      32             // batches per CTA
#define THREADS 512            // 16 threads per batch, 4 outputs each
#define WPAD    520            // per-batch stride (floats) of duplicated-w buffer; 520%32=8 -> no bank conflict between the warp's 2 batches
#define CSTEP   16384          // floats in one mid-core step (64*4*64)

// Dynamic smem layout (floats):
//   [0, 2*CSTEP)            : C double buffer (2 x 64KB)
//   [2*CSTEP, +TB*WPAD)     : duplicated w buffer {w[k],w[k]} pairs per batch
#define SMEM_FLOATS (2*CSTEP + TB*WPAD)
#define SMEM_BYTES  (SMEM_FLOATS * 4)

extern __shared__ float smem_f[];

__device__ __forceinline__ uint64_t fma2(uint64_t a, uint64_t b, uint64_t c) {
    uint64_t d;
    asm("fma.rn.f32x2 %0, %1, %2, %3;" : "=l"(d) : "l"(a), "l"(b), "l"(c));
    return d;
}

__device__ __forceinline__ uint32_t smem_u32(const void* p) {
    return (uint32_t)__cvta_generic_to_shared(p);
}

__device__ __forceinline__ void cp_async16(uint32_t dst, const void* src) {
    asm volatile("cp.async.cg.shared.global [%0], [%1], 16;\n" :: "r"(dst), "l"(src));
}

__global__ void __launch_bounds__(THREADS, 1)
tt_chain_kernel(const float* __restrict__ x,    // [B, 128, 4]
                const float* __restrict__ fc,   // [4, 64]
                const float* __restrict__ mc,   // [126, 64, 4, 64]
                const float* __restrict__ lc,   // [64, 4]
                float* __restrict__ out)        // [B, 1]
{
    float* Cbuf = smem_f;                  // 2*CSTEP floats
    float* wbuf = smem_f + 2*CSTEP;        // TB*WPAD floats

    const int tid = threadIdx.x;
    const int bl  = tid >> 4;              // local batch 0..31
    const int rq  = tid & 15;              // r-group 0..15
    const int r0  = rq * 4;                // first of 4 outputs
    const int b   = blockIdx.x * TB + bl;

    const float* xb = x + (size_t)b * (LEN * FEATD);

    // ---- prefetch C[0] into buffer 0 ----
    {
        uint32_t dst = smem_u32(Cbuf);
        #pragma unroll
        for (int j = 0; j < 8; ++j) {
            int idx = j * THREADS + tid;                 // 0..4095 (16B chunks)
            cp_async16(dst + idx * 16, mc + idx * 4);
        }
        asm volatile("cp.async.commit_group;\n");
    }

    // ---- init: v0 from first_core & x[.,0,.], then w0 (uses x[.,1,.]) ----
    {
        float4 x0 = *(const float4*)(xb + 0);
        float4 x1 = *(const float4*)(xb + FEATD);
        float v[4];
        #pragma unroll
        for (int j = 0; j < 4; ++j) {
            int l = r0 + j;
            v[j] = fc[0*RANK + l] * x0.x + fc[1*RANK + l] * x0.y
                 + fc[2*RANK + l] * x0.z + fc[3*RANK + l] * x0.w;
        }
        float4* wp = (float4*)(wbuf + bl * WPAD + r0 * 8);
        #pragma unroll
        for (int j = 0; j < 4; ++j) {
            float a0 = v[j] * x1.x, a1 = v[j] * x1.y;
            float a2 = v[j] * x1.z, a3 = v[j] * x1.w;
            wp[2*j + 0] = make_float4(a0, a0, a1, a1);
            wp[2*j + 1] = make_float4(a2, a2, a3, a3);
        }
    }

    // ---- main sequential chain ----
    #pragma unroll 1
    for (int s = 0; s < NSTEP; ++s) {
        // prefetch C[s+1] into the other buffer, wait for C[s]
        if (s + 1 < NSTEP) {
            uint32_t dst = smem_u32(Cbuf + ((s + 1) & 1) * CSTEP);
            const float* src = mc + (size_t)(s + 1) * CSTEP;
            #pragma unroll
            for (int j = 0; j < 8; ++j) {
                int idx = j * THREADS + tid;
                cp_async16(dst + idx * 16, src + idx * 4);
            }
            asm volatile("cp.async.commit_group;\n");
            asm volatile("cp.async.wait_group 1;\n");
        } else {
            asm volatile("cp.async.wait_group 0;\n");
        }
        __syncthreads();   // C[s] visible to all; w_s writes visible to all

        // prefetch next-site x early so its latency hides under the k-loop
        float4 xn;
        if (s + 1 < NSTEP) xn = *(const float4*)(xb + (s + 2) * FEATD);
        else               xn = *(const float4*)(xb + (LEN - 1) * FEATD);

        // inner contraction: v_new[r0..r0+3] = sum_k w[k] * C[k][r0..r0+3]
        const float* Cs = Cbuf + (s & 1) * CSTEP + r0;
        const float* wp = wbuf + bl * WPAD;
        uint64_t acc0 = 0ull, acc1 = 0ull;   // {0.f,0.f}
        #pragma unroll 8
        for (int k = 0; k < KDIM; ++k) {
            uint64_t   wkk = *(const uint64_t*)(wp + 2 * k);       // {w,w} LDS.64
            ulonglong2 c   = *(const ulonglong2*)(Cs + k * RANK);  // LDS.128
            acc0 = fma2(wkk, c.x, acc0);
            acc1 = fma2(wkk, c.y, acc1);
        }
        __syncthreads();   // all reads of wbuf / Cbuf[s&1] complete

        float2 p0 = *reinterpret_cast<float2*>(&acc0);
        float2 p1 = *reinterpret_cast<float2*>(&acc1);
        float vnew[4] = { p0.x, p0.y, p1.x, p1.y };

        if (s + 1 < NSTEP) {
            // build w_{s+1}[4l+i] = v_{s+1}[l] * x[b, s+2, i], duplicated pairs
            float4* wpw = (float4*)(wbuf + bl * WPAD + r0 * 8);
            #pragma unroll
            for (int j = 0; j < 4; ++j) {
                float a0 = vnew[j] * xn.x, a1 = vnew[j] * xn.y;
                float a2 = vnew[j] * xn.z, a3 = vnew[j] * xn.w;
                wpw[2*j + 0] = make_float4(a0, a0, a1, a1);
                wpw[2*j + 1] = make_float4(a2, a2, a3, a3);
            }
        } else {
            // final contraction against last_core with x[., 127, .]
            float part = 0.f;
            #pragma unroll
            for (int j = 0; j < 4; ++j) {
                int r = r0 + j;
                float4 lcr = *(const float4*)(lc + r * FEATD);
                float lv = lcr.x * xn.x + lcr.y * xn.y + lcr.z * xn.z + lcr.w * xn.w;
                part += vnew[j] * lv;
            }
            // reduce over the 16 threads of this batch (lanes stay in one warp half)
            #pragma unroll
            for (int off = 8; off > 0; off >>= 1)
                part += __shfl_down_sync(0xffffffffu, part, off, 16);
            if (rq == 0) out[b] = part;
        }
    }
}

extern "C" void kernel_launch(void* const* d_in, const int* in_sizes, int n_in,
                              void* d_out, int out_size) {
    const float* x  = (const float*)d_in[0];   // input_data [4096,128,4]
    const float* fc = (const float*)d_in[1];   // first_core [4,64]
    const float* mc = (const float*)d_in[2];   // mid_cores  [126,64,4,64]
    const float* lc = (const float*)d_in[3];   // last_core  [64,4]
    float* out = (float*)d_out;

    cudaFuncSetAttribute(tt_chain_kernel,
                         cudaFuncAttributeMaxDynamicSharedMemorySize, SMEM_BYTES);

    tt_chain_kernel<<<BATCH / TB, THREADS, SMEM_BYTES>>>(x, fc, mc, lc, out);
}

// round 2
// speedup vs baseline: 1.0012x; 1.0012x over previous
#include <cuda_runtime.h>
#include <cstdint>

// Tensor-train chain contraction, fp32, packed-f32x2 CUDA-core kernel.
//   v0[b,r]     = sum_i fc[i,r] * x[b,0,i]
//   step s:     v[b,r] <- sum_{l,i} v[b,l] * x[b,s+1,i] * mc[s,l,i,r]
//   out[b]      = sum_r v[b,r] * (sum_i lc[r,i] * x[b,127,i])
//
// Reformulated per step as v_new = w @ C_s with w[k=4l+i] = v[l]*x[i] (K=256, N=64).

#define BATCH   4096
#define LEN     128
#define FEATD   4
#define RANK    64
#define NSTEP   126
#define KDIM    256            // RANK*FEATD
#define TB      32             // batches per CTA
#define THREADS 512            // 16 threads per batch, 4 outputs each
#define WPAD    520            // per-batch stride (floats) of duplicated-w buffer; 520%32=8 -> no bank conflict between the warp's 2 batches
#define CSTEP   16384          // floats in one mid-core step (64*4*64)

// Dynamic smem layout (floats):
//   [0, 2*CSTEP)            : C double buffer (2 x 64KB)
//   [2*CSTEP, +TB*WPAD)     : duplicated w buffer {w[k],w[k]} pairs per batch
#define SMEM_FLOATS (2*CSTEP + TB*WPAD)
#define SMEM_BYTES  (SMEM_FLOATS * 4)

extern __shared__ float smem_f[];

__device__ __forceinline__ uint64_t fma2(uint64_t a, uint64_t b, uint64_t c) {
    uint64_t d;
    asm("fma.rn.f32x2 %0, %1, %2, %3;" : "=l"(d) : "l"(a), "l"(b), "l"(c));
    return d;
}

__device__ __forceinline__ uint32_t smem_u32(const void* p) {
    return (uint32_t)__cvta_generic_to_shared(p);
}

__device__ __forceinline__ void cp_async16(uint32_t dst, const void* src) {
    asm volatile("cp.async.cg.shared.global [%0], [%1], 16;\n" :: "r"(dst), "l"(src));
}

__global__ void __launch_bounds__(THREADS, 1)
tt_chain_kernel(const float* __restrict__ x,    // [B, 128, 4]
                const float* __restrict__ fc,   // [4, 64]
                const float* __restrict__ mc,   // [126, 64, 4, 64]
                const float* __restrict__ lc,   // [64, 4]
                float* __restrict__ out)        // [B, 1]
{
    float* Cbuf = smem_f;                  // 2*CSTEP floats
    float* wbuf = smem_f + 2*CSTEP;        // TB*WPAD floats

    const int tid = threadIdx.x;
    const int bl  = tid >> 4;              // local batch 0..31
    const int rq  = tid & 15;              // r-group 0..15
    const int r0  = rq * 4;                // first of 4 outputs
    const int b   = blockIdx.x * TB + bl;

    const float* xb = x + (size_t)b * (LEN * FEATD);

    // ---- prefetch C[0] into buffer 0 ----
    {
        uint32_t dst = smem_u32(Cbuf);
        #pragma unroll
        for (int j = 0; j < 8; ++j) {
            int idx = j * THREADS + tid;                 // 0..4095 (16B chunks)
            cp_async16(dst + idx * 16, mc + idx * 4);
        }
        asm volatile("cp.async.commit_group;\n");
    }

    // ---- init: v0 from first_core & x[.,0,.], then w0 (uses x[.,1,.]) ----
    {
        float4 x0 = *(const float4*)(xb + 0);
        float4 x1 = *(const float4*)(xb + FEATD);
        float v[4];
        #pragma unroll
        for (int j = 0; j < 4; ++j) {
            int l = r0 + j;
            v[j] = fc[0*RANK + l] * x0.x + fc[1*RANK + l] * x0.y
                 + fc[2*RANK + l] * x0.z + fc[3*RANK + l] * x0.w;
        }
        float4* wp = (float4*)(wbuf + bl * WPAD + r0 * 8);
        #pragma unroll
        for (int j = 0; j < 4; ++j) {
            float a0 = v[j] * x1.x, a1 = v[j] * x1.y;
            float a2 = v[j] * x1.z, a3 = v[j] * x1.w;
            wp[2*j + 0] = make_float4(a0, a0, a1, a1);
            wp[2*j + 1] = make_float4(a2, a2, a3, a3);
        }
    }

    // ---- main sequential chain ----
    #pragma unroll 1
    for (int s = 0; s < NSTEP; ++s) {
        // prefetch C[s+1] into the other buffer, wait for C[s]
        if (s + 1 < NSTEP) {
            uint32_t dst = smem_u32(Cbuf + ((s + 1) & 1) * CSTEP);
            const float* src = mc + (size_t)(s + 1) * CSTEP;
            #pragma unroll
            for (int j = 0; j < 8; ++j) {
                int idx = j * THREADS + tid;
                cp_async16(dst + idx * 16, src + idx * 4);
            }
            asm volatile("cp.async.commit_group;\n");
            asm volatile("cp.async.wait_group 1;\n");
        } else {
            asm volatile("cp.async.wait_group 0;\n");
        }
        __syncthreads();   // C[s] visible to all; w_s writes visible to all

        // prefetch next-site x early so its latency hides under the k-loop
        float4 xn;
        if (s + 1 < NSTEP) xn = *(const float4*)(xb + (s + 2) * FEATD);
        else               xn = *(const float4*)(xb + (LEN - 1) * FEATD);

        // inner contraction: v_new[r0..r0+3] = sum_k w[k] * C[k][r0..r0+3]
        const float* Cs = Cbuf + (s & 1) * CSTEP + r0;
        const float* wp = wbuf + bl * WPAD;
        uint64_t acc0 = 0ull, acc1 = 0ull;   // {0.f,0.f}
        #pragma unroll 8
        for (int k = 0; k < KDIM; ++k) {
            uint64_t   wkk = *(const uint64_t*)(wp + 2 * k);       // {w,w} LDS.64
            ulonglong2 c   = *(const ulonglong2*)(Cs + k * RANK);  // LDS.128
            acc0 = fma2(wkk, c.x, acc0);
            acc1 = fma2(wkk, c.y, acc1);
        }
        __syncthreads();   // all reads of wbuf / Cbuf[s&1] complete

        float2 p0 = *reinterpret_cast<float2*>(&acc0);
        float2 p1 = *reinterpret_cast<float2*>(&acc1);
        float vnew[4] = { p0.x, p0.y, p1.x, p1.y };

        if (s + 1 < NSTEP) {
            // build w_{s+1}[4l+i] = v_{s+1}[l] * x[b, s+2, i], duplicated pairs
            float4* wpw = (float4*)(wbuf + bl * WPAD + r0 * 8);
            #pragma unroll
            for (int j = 0; j < 4; ++j) {
                float a0 = vnew[j] * xn.x, a1 = vnew[j] * xn.y;
                float a2 = vnew[j] * xn.z, a3 = vnew[j] * xn.w;
                wpw[2*j + 0] = make_float4(a0, a0, a1, a1);
                wpw[2*j + 1] = make_float4(a2, a2, a3, a3);
            }
        } else {
            // final contraction against last_core with x[., 127, .]
            float part = 0.f;
            #pragma unroll
            for (int j = 0; j < 4; ++j) {
                int r = r0 + j;
                float4 lcr = *(const float4*)(lc + r * FEATD);
                float lv = lcr.x * xn.x + lcr.y * xn.y + lcr.z * xn.z + lcr.w * xn.w;
                part += vnew[j] * lv;
            }
            // reduce over the 16 threads of this batch (lanes stay in one warp half)
            #pragma unroll
            for (int off = 8; off > 0; off >>= 1)
                part += __shfl_down_sync(0xffffffffu, part, off, 16);
            if (rq == 0) out[b] = part;
        }
    }
}

extern "C" void kernel_launch(void* const* d_in, const int* in_sizes, int n_in,
                              void* d_out, int out_size) {
    const float* x  = (const float*)d_in[0];   // input_data [4096,128,4]
    const float* fc = (const float*)d_in[1];   // first_core [4,64]
    const float* mc = (const float*)d_in[2];   // mid_cores  [126,64,4,64]
    const float* lc = (const float*)d_in[3];   // last_core  [64,4]
    float* out = (float*)d_out;

    cudaFuncSetAttribute(tt_chain_kernel,
                         cudaFuncAttributeMaxDynamicSharedMemorySize, SMEM_BYTES);

    tt_chain_kernel<<<BATCH / TB, THREADS, SMEM_BYTES>>>(x, fc, mc, lc, out);
}

// round 3
// speedup vs baseline: 2.6181x; 2.6150x over previous
#include <cuda_runtime.h>
#include <cstdint>

// Tensor-train chain, fp32, packed-f32x2, crossbar-optimized.
// Step s: v_{s+1}[b][r] = sum_{l,i} v_s[b][l] * x[b][s+1][i] * C_s[l][i][r]
// Thread tile: 4 batches x 4 r. Streams dup-v from smem (8B/batch/l),
// builds w = v*x in registers (MUL2), C plain from smem.

#define BATCH   4096
#define LEN     128
#define RANK    64
#define NSTEP   126
#define CSTEP   16384          // floats per mid-core step (256*64)
#define TB      32             // batches per CTA
#define THREADS 128            // 4 warps
#define VROW    34             // float2 per vdup row (32 + 2 pad, keeps 16B align)

// smem (floats): C double buffer (2*CSTEP) | vdup 64*VROW float2 | part 16*36
#define SMEM_FLOATS (2*CSTEP + 64*VROW*2 + 16*36)
#define SMEM_BYTES  (SMEM_FLOATS * 4)

extern __shared__ float smem_f[];

__device__ __forceinline__ uint64_t fma2(uint64_t a, uint64_t b, uint64_t c) {
    uint64_t d;
    asm("fma.rn.f32x2 %0, %1, %2, %3;" : "=l"(d) : "l"(a), "l"(b), "l"(c));
    return d;
}
__device__ __forceinline__ uint64_t mul2(uint64_t a, uint64_t b) {
    uint64_t d;
    asm("mul.rn.f32x2 %0, %1, %2;" : "=l"(d) : "l"(a), "l"(b));
    return d;
}
__device__ __forceinline__ uint64_t dup2(float f) {
    uint64_t d;
    asm("mov.b64 %0, {%1, %1};" : "=l"(d) : "f"(f));
    return d;
}
__device__ __forceinline__ float acc_get(uint64_t a, int half) {
    float2 f = *reinterpret_cast<float2*>(&a);
    return half ? f.y : f.x;
}
__device__ __forceinline__ uint32_t smem_u32(const void* p) {
    return (uint32_t)__cvta_generic_to_shared(p);
}
__device__ __forceinline__ void cp_async16(uint32_t dst, const void* src) {
    asm volatile("cp.async.cg.shared.global [%0], [%1], 16;\n" :: "r"(dst), "l"(src));
}

__global__ void __launch_bounds__(THREADS, 1)
tt_chain_kernel(const float* __restrict__ x,    // [B, 128, 4]
                const float* __restrict__ fc,   // [4, 64]
                const float* __restrict__ mc,   // [126, 64, 4, 64]
                const float* __restrict__ lc,   // [64, 4]
                float* __restrict__ out)        // [B, 1]
{
    float*  Cbuf = smem_f;                          // 2*CSTEP floats
    float2* vdup = (float2*)(smem_f + 2*CSTEP);     // [64][VROW] dup-v
    float*  part = (float*)(vdup + 64*VROW);        // [16][36] epilogue partials

    const int tid  = threadIdx.x;
    const int warp = tid >> 5;
    const int lane = tid & 31;
    const int bg   = lane >> 2;            // 0..7  -> 4 batches each
    const int rg   = lane & 3;             // 0..3
    const int rbase = warp * 16 + rg * 4;  // this thread's 4 r outputs
    const int bloc  = bg * 4;              // local batch base
    const int gb    = blockIdx.x * TB + bloc;

    // ---- prefetch C[0] ----
    {
        uint32_t dst = smem_u32(Cbuf);
        #pragma unroll
        for (int j = 0; j < 32; ++j) {
            int idx = j * THREADS + tid;           // 4096 16B chunks
            cp_async16(dst + idx * 16, mc + idx * 4);
        }
        asm volatile("cp.async.commit_group;\n");
    }

    // ---- v0[b][r] = sum_i fc[i][r] * x[b][0][i]; write dup to vdup ----
    {
        float4 x0[4];
        #pragma unroll
        for (int m = 0; m < 4; ++m)
            x0[m] = *(const float4*)(x + (size_t)(gb + m) * (LEN * 4));
        float4 fcv[4];      // fcv[i] = fc[i][rbase..rbase+3]
        #pragma unroll
        for (int i = 0; i < 4; ++i)
            fcv[i] = *(const float4*)(fc + i * RANK + rbase);

        #pragma unroll
        for (int j = 0; j < 4; ++j) {
            float vj[4];
            #pragma unroll
            for (int m = 0; m < 4; ++m) {
                const float* fj = (const float*)&fcv[0];   // not used; compute below
                (void)fj;
                float fc0 = ((const float*)&fcv[0])[j];
                float fc1 = ((const float*)&fcv[1])[j];
                float fc2 = ((const float*)&fcv[2])[j];
                float fc3 = ((const float*)&fcv[3])[j];
                vj[m] = fc0 * x0[m].x + fc1 * x0[m].y + fc2 * x0[m].z + fc3 * x0[m].w;
            }
            float4* dst = (float4*)(vdup + (rbase + j) * VROW + bloc);
            dst[0] = make_float4(vj[0], vj[0], vj[1], vj[1]);
            dst[1] = make_float4(vj[2], vj[2], vj[3], vj[3]);
        }
    }

    // ---- main sequential chain ----
    #pragma unroll 1
    for (int s = 0; s < NSTEP; ++s) {
        // prefetch C[s+1], wait for C[s]
        if (s + 1 < NSTEP) {
            uint32_t dst = smem_u32(Cbuf + ((s + 1) & 1) * CSTEP);
            const float* src = mc + (size_t)(s + 1) * CSTEP;
            #pragma unroll
            for (int j = 0; j < 32; ++j) {
                int idx = j * THREADS + tid;
                cp_async16(dst + idx * 16, src + idx * 4);
            }
            asm volatile("cp.async.commit_group;\n");
            asm volatile("cp.async.wait_group 1;\n");
        } else {
            asm volatile("cp.async.wait_group 0;\n");
        }

        // per-batch x at site s+1, duplicated into registers
        uint64_t x2[4][4];
        {
            #pragma unroll
            for (int m = 0; m < 4; ++m) {
                float4 xs = *(const float4*)(x + (size_t)(gb + m) * (LEN * 4) + (s + 1) * 4);
                x2[m][0] = dup2(xs.x);
                x2[m][1] = dup2(xs.y);
                x2[m][2] = dup2(xs.z);
                x2[m][3] = dup2(xs.w);
            }
        }

        __syncthreads();   // C[s] visible; vdup (v_s) visible

        const float* Cs = Cbuf + (s & 1) * CSTEP + rbase;
        const float2* vr = vdup + bloc;

        uint64_t acc[4][2];
        #pragma unroll
        for (int m = 0; m < 4; ++m) { acc[m][0] = 0ull; acc[m][1] = 0ull; }

        #pragma unroll 4
        for (int l = 0; l < 64; ++l) {
            // dup-v for this thread's 4 batches: {v0,v0,v1,v1},{v2,v2,v3,v3}
            ulonglong2 va = *(const ulonglong2*)(vr + l * VROW);
            ulonglong2 vb = *(const ulonglong2*)(vr + l * VROW + 2);
            uint64_t v2[4] = { va.x, va.y, vb.x, vb.y };
            #pragma unroll
            for (int i = 0; i < 4; ++i) {
                ulonglong2 c = *(const ulonglong2*)(Cs + (4 * l + i) * RANK);
                #pragma unroll
                for (int m = 0; m < 4; ++m) {
                    uint64_t w2 = mul2(v2[m], x2[m][i]);
                    acc[m][0] = fma2(w2, c.x, acc[m][0]);
                    acc[m][1] = fma2(w2, c.y, acc[m][1]);
                }
            }
        }

        __syncthreads();   // all reads of vdup / Cbuf[s&1] done

        if (s + 1 < NSTEP) {
            // write v_{s+1} duplicated: vdup[rbase+j][bloc+m] = {v,v}
            #pragma unroll
            for (int j = 0; j < 4; ++j) {
                float v0 = acc_get(acc[0][j >> 1], j & 1);
                float v1 = acc_get(acc[1][j >> 1], j & 1);
                float v2s = acc_get(acc[2][j >> 1], j & 1);
                float v3 = acc_get(acc[3][j >> 1], j & 1);
                float4* dst = (float4*)(vdup + (rbase + j) * VROW + bloc);
                dst[0] = make_float4(v0, v0, v1, v1);
                dst[1] = make_float4(v2s, v2s, v3, v3);
            }
        } else {
            // epilogue: out[b] = sum_r v[b][r] * (sum_i lc[r][i]*x[b][127][i])
            float4 xe[4];
            #pragma unroll
            for (int m = 0; m < 4; ++m)
                xe[m] = *(const float4*)(x + (size_t)(gb + m) * (LEN * 4) + 127 * 4);
            float4 lcv[4];
            #pragma unroll
            for (int j = 0; j < 4; ++j)
                lcv[j] = *(const float4*)(lc + (rbase + j) * 4);

            float pm[4] = {0.f, 0.f, 0.f, 0.f};
            #pragma unroll
            for (int j = 0; j < 4; ++j) {
                #pragma unroll
                for (int m = 0; m < 4; ++m) {
                    float lv = lcv[j].x * xe[m].x + lcv[j].y * xe[m].y
                             + lcv[j].z * xe[m].z + lcv[j].w * xe[m].w;
                    pm[m] += acc_get(acc[m][j >> 1], j & 1) * lv;
                }
            }
            int slot = warp * 4 + rg;      // 16 r-group slots
            *(float4*)(part + slot * 36 + bloc) = make_float4(pm[0], pm[1], pm[2], pm[3]);

            __syncthreads();
            if (tid < TB) {
                float sum = 0.f;
                #pragma unroll
                for (int q = 0; q < 16; ++q) sum += part[q * 36 + tid];
                out[blockIdx.x * TB + tid] = sum;
            }
        }
    }
}

extern "C" void kernel_launch(void* const* d_in, const int* in_sizes, int n_in,
                              void* d_out, int out_size) {
    const float* x  = (const float*)d_in[0];   // input_data [4096,128,4]
    const float* fc = (const float*)d_in[1];   // first_core [4,64]
    const float* mc = (const float*)d_in[2];   // mid_cores  [126,64,4,64]
    const float* lc = (const float*)d_in[3];   // last_core  [64,4]
    float* out = (float*)d_out;

    cudaFuncSetAttribute(tt_chain_kernel,
                         cudaFuncAttributeMaxDynamicSharedMemorySize, SMEM_BYTES);

    tt_chain_kernel<<<BATCH / TB, THREADS, SMEM_BYTES>>>(x, fc, mc, lc, out);
}

// round 4
// speedup vs baseline: 3.4379x; 1.3132x over previous
#include <cuda_runtime.h>
#include <cstdint>

// Tensor-train chain, fp32, packed-f32x2, batch-pair + reordered accumulation.
// Step s: t[i][r] = sum_l v[l]*C_s[l][i][r]   (pure fma2, batch-pairs in f32x2)
//         v'[r]   = sum_i x[b][s+1][i]*t[i][r]
// Thread tile: 8 batches (4 pairs) x 2 r. 256 threads = 8 warps; warps 0-3 do
// l in [0,32) ("half A"), warps 4-7 do l in [32,64) ("half B"); per-step
// partial-v reduction A->B through smem scratch.

#define BATCH   4096
#define LEN     128
#define RANK    64
#define NSTEP   126
#define CSTEP   16384          // floats per mid-core step (256*64)
#define TB      32             // batches per CTA
#define THREADS 256
#define VROW    18             // float2 per v row (16 + 2 pad), keeps 16B align

// smem (floats): C double buffer | vbuf [64][VROW] float2 | scratch same
#define SMEM_FLOATS (2*CSTEP + 2*(64*VROW*2))
#define SMEM_BYTES  (SMEM_FLOATS * 4)

extern __shared__ float smem_f[];

__device__ __forceinline__ uint64_t fma2(uint64_t a, uint64_t b, uint64_t c) {
    uint64_t d;
    asm("fma.rn.f32x2 %0, %1, %2, %3;" : "=l"(d) : "l"(a), "l"(b), "l"(c));
    return d;
}
__device__ __forceinline__ uint64_t mul2(uint64_t a, uint64_t b) {
    uint64_t d;
    asm("mul.rn.f32x2 %0, %1, %2;" : "=l"(d) : "l"(a), "l"(b));
    return d;
}
__device__ __forceinline__ uint64_t add2(uint64_t a, uint64_t b) {
    uint64_t d;
    asm("add.rn.f32x2 %0, %1, %2;" : "=l"(d) : "l"(a), "l"(b));
    return d;
}
__device__ __forceinline__ uint64_t dup2(float f) {
    uint64_t d;
    asm("mov.b64 %0, {%1, %1};" : "=l"(d) : "f"(f));
    return d;
}
__device__ __forceinline__ uint64_t pack2(float a, float b) {
    uint64_t d;
    asm("mov.b64 %0, {%1, %2};" : "=l"(d) : "f"(a), "f"(b));
    return d;
}
__device__ __forceinline__ float2 u2f(uint64_t a) {
    return *reinterpret_cast<float2*>(&a);
}
__device__ __forceinline__ uint32_t smem_u32(const void* p) {
    return (uint32_t)__cvta_generic_to_shared(p);
}
__device__ __forceinline__ void cp_async16(uint32_t dst, const void* src) {
    asm volatile("cp.async.cg.shared.global [%0], [%1], 16;\n" :: "r"(dst), "l"(src));
}

__global__ void __launch_bounds__(THREADS, 1)
tt_chain_kernel(const float* __restrict__ x,    // [B, 128, 4]
                const float* __restrict__ fc,   // [4, 64]
                const float* __restrict__ mc,   // [126, 64, 4, 64]
                const float* __restrict__ lc,   // [64, 4]
                float* __restrict__ out)        // [B, 1]
{
    float*  Cbuf = smem_f;                         // 2*CSTEP floats
    float2* vbuf = (float2*)(smem_f + 2*CSTEP);    // [64][VROW] batch-pair v
    float2* scr  = vbuf + 64*VROW;                 // partial-v scratch, same shape

    const int tid  = threadIdx.x;
    const int warp = tid >> 5;
    const int lane = tid & 31;
    const int half = warp >> 2;            // 0: l in [0,32) ; 1: l in [32,64)
    const int bg   = warp & 3;             // 8 batches per bg
    const int r0   = 2 * lane;             // this thread's 2 r outputs
    const int gb0  = blockIdx.x * TB + bg * 8;
    const float* xb0 = x + (size_t)gb0 * (LEN * 4);

    // ---- prefetch C[0] ----
    {
        uint32_t dst = smem_u32(Cbuf);
        #pragma unroll
        for (int j = 0; j < 16; ++j) {
            int idx = j * THREADS + tid;           // 4096 16B chunks
            cp_async16(dst + idx * 16, mc + idx * 4);
        }
        asm volatile("cp.async.commit_group;\n");
    }

    // ---- prologue: half A computes v0 pairs and stores vbuf ----
    if (half == 0) {
        #pragma unroll
        for (int p = 0; p < 4; ++p) {
            const float* xa = xb0 + (size_t)(2 * p) * (LEN * 4);
            float4 x0a = *(const float4*)xa;
            float4 x0b = *(const float4*)(xa + LEN * 4);
            #pragma unroll
            for (int j = 0; j < 2; ++j) {
                int r = r0 + j;
                float f0 = fc[r], f1 = fc[RANK + r], f2 = fc[2*RANK + r], f3 = fc[3*RANK + r];
                float va = f0*x0a.x + f1*x0a.y + f2*x0a.z + f3*x0a.w;
                float vb = f0*x0b.x + f1*x0b.y + f2*x0b.z + f3*x0b.w;
                vbuf[r * VROW + 4*bg + p] = make_float2(va, vb);
            }
        }
    }

    const int lbase = half * 32;

    // ---- main sequential chain ----
    #pragma unroll 1
    for (int s = 0; s < NSTEP; ++s) {
        // prefetch C[s+1], wait for C[s]
        if (s + 1 < NSTEP) {
            uint32_t dst = smem_u32(Cbuf + ((s + 1) & 1) * CSTEP);
            const float* src = mc + (size_t)(s + 1) * CSTEP;
            #pragma unroll
            for (int j = 0; j < 16; ++j) {
                int idx = j * THREADS + tid;
                cp_async16(dst + idx * 16, src + idx * 4);
            }
            asm volatile("cp.async.commit_group;\n");
            asm volatile("cp.async.wait_group 1;\n");
        } else {
            asm volatile("cp.async.wait_group 0;\n");
        }
        __syncthreads();   // C[s] ready; vbuf (v_s) ready

        const float*  Cs = Cbuf + (s & 1) * CSTEP;
        const float2* vb = vbuf + 4 * bg;

        uint64_t t[4][4][2];   // [i][pair][j] f32x2 over {b0,b1}

        // first l: mul2 (initializes t)
        {
            const int l = lbase;
            const float2* vrow = vb + l * VROW;
            ulonglong2 va = *(const ulonglong2*)(vrow);
            ulonglong2 vq = *(const ulonglong2*)(vrow + 2);
            uint64_t vp[4] = { va.x, va.y, vq.x, vq.y };
            #pragma unroll
            for (int i = 0; i < 4; ++i) {
                float2 cl = *(const float2*)(Cs + (4*l + i) * RANK + r0);
                uint64_t c0 = dup2(cl.x), c1 = dup2(cl.y);
                #pragma unroll
                for (int p = 0; p < 4; ++p) {
                    t[i][p][0] = mul2(vp[p], c0);
                    t[i][p][1] = mul2(vp[p], c1);
                }
            }
        }
        // remaining 31 l values: fma2
        #pragma unroll 4
        for (int ll = 1; ll < 32; ++ll) {
            const int l = lbase + ll;
            const float2* vrow = vb + l * VROW;
            ulonglong2 va = *(const ulonglong2*)(vrow);
            ulonglong2 vq = *(const ulonglong2*)(vrow + 2);
            uint64_t vp[4] = { va.x, va.y, vq.x, vq.y };
            #pragma unroll
            for (int i = 0; i < 4; ++i) {
                float2 cl = *(const float2*)(Cs + (4*l + i) * RANK + r0);
                uint64_t c0 = dup2(cl.x), c1 = dup2(cl.y);
                #pragma unroll
                for (int p = 0; p < 4; ++p) {
                    t[i][p][0] = fma2(vp[p], c0, t[i][p][0]);
                    t[i][p][1] = fma2(vp[p], c1, t[i][p][1]);
                }
            }
        }

        // ---- combine with x[., s+1, .] : vn = sum_i xpair[i] * t[i] ----
        uint64_t vn[4][2];
        #pragma unroll
        for (int p = 0; p < 4; ++p) {
            const float* xa = xb0 + (size_t)(2 * p) * (LEN * 4) + (size_t)(s + 1) * 4;
            float4 xsa = *(const float4*)xa;
            float4 xsb = *(const float4*)(xa + LEN * 4);
            uint64_t xp0 = pack2(xsa.x, xsb.x);
            uint64_t xp1 = pack2(xsa.y, xsb.y);
            uint64_t xp2 = pack2(xsa.z, xsb.z);
            uint64_t xp3 = pack2(xsa.w, xsb.w);
            #pragma unroll
            for (int j = 0; j < 2; ++j) {
                uint64_t v = mul2(xp0, t[0][p][j]);
                v = fma2(xp1, t[1][p][j], v);
                v = fma2(xp2, t[2][p][j], v);
                v = fma2(xp3, t[3][p][j], v);
                vn[p][j] = v;
            }
        }

        // ---- cross-half reduction: A -> scratch, B adds and finalizes ----
        if (half == 0) {
            #pragma unroll
            for (int j = 0; j < 2; ++j) {
                float2 a = u2f(vn[0][j]), b = u2f(vn[1][j]);
                float2 c = u2f(vn[2][j]), d = u2f(vn[3][j]);
                float4* dst = (float4*)(scr + (r0 + j) * VROW + 4*bg);
                dst[0] = make_float4(a.x, a.y, b.x, b.y);
                dst[1] = make_float4(c.x, c.y, d.x, d.y);
            }
        }
        __syncthreads();   // A's partials visible; also fences vbuf reads

        if (half == 1) {
            #pragma unroll
            for (int j = 0; j < 2; ++j) {
                const float4* sp = (const float4*)(scr + (r0 + j) * VROW + 4*bg);
                float4 s0 = sp[0], s1 = sp[1];
                vn[0][j] = add2(vn[0][j], pack2(s0.x, s0.y));
                vn[1][j] = add2(vn[1][j], pack2(s0.z, s0.w));
                vn[2][j] = add2(vn[2][j], pack2(s1.x, s1.y));
                vn[3][j] = add2(vn[3][j], pack2(s1.z, s1.w));
            }

            if (s + 1 < NSTEP) {
                // store v_{s+1} pairs for next step
                #pragma unroll
                for (int j = 0; j < 2; ++j) {
                    float2 a = u2f(vn[0][j]), b = u2f(vn[1][j]);
                    float2 c = u2f(vn[2][j]), d = u2f(vn[3][j]);
                    float4* dst = (float4*)(vbuf + (r0 + j) * VROW + 4*bg);
                    dst[0] = make_float4(a.x, a.y, b.x, b.y);
                    dst[1] = make_float4(c.x, c.y, d.x, d.y);
                }
            } else {
                // epilogue: out[b] = sum_r v[b][r] * (sum_i lc[r][i]*x[b][127][i])
                float2 accp[4];
                #pragma unroll
                for (int p = 0; p < 4; ++p) {
                    const float* xa = xb0 + (size_t)(2 * p) * (LEN * 4) + 127 * 4;
                    float4 xe0 = *(const float4*)xa;
                    float4 xe1 = *(const float4*)(xa + LEN * 4);
                    float2 ac = make_float2(0.f, 0.f);
                    #pragma unroll
                    for (int j = 0; j < 2; ++j) {
                        int r = r0 + j;
                        float4 l4 = *(const float4*)(lc + r * 4);
                        float lv0 = l4.x*xe0.x + l4.y*xe0.y + l4.z*xe0.z + l4.w*xe0.w;
                        float lv1 = l4.x*xe1.x + l4.y*xe1.y + l4.z*xe1.z + l4.w*xe1.w;
                        float2 vv = u2f(vn[p][j]);
                        ac.x += vv.x * lv0;
                        ac.y += vv.y * lv1;
                    }
                    accp[p] = ac;
                }
                // reduce over the 32 lanes (r dimension)
                #pragma unroll
                for (int off = 16; off > 0; off >>= 1) {
                    #pragma unroll
                    for (int p = 0; p < 4; ++p) {
                        accp[p].x += __shfl_down_sync(0xffffffffu, accp[p].x, off);
                        accp[p].y += __shfl_down_sync(0xffffffffu, accp[p].y, off);
                    }
                }
                if (lane == 0) {
                    #pragma unroll
                    for (int p = 0; p < 4; ++p) {
                        out[gb0 + 2*p + 0] = accp[p].x;
                        out[gb0 + 2*p + 1] = accp[p].y;
                    }
                }
            }
        }
    }
}

extern "C" void kernel_launch(void* const* d_in, const int* in_sizes, int n_in,
                              void* d_out, int out_size) {
    const float* x  = (const float*)d_in[0];   // input_data [4096,128,4]
    const float* fc = (const float*)d_in[1];   // first_core [4,64]
    const float* mc = (const float*)d_in[2];   // mid_cores  [126,64,4,64]
    const float* lc = (const float*)d_in[3];   // last_core  [64,4]
    float* out = (float*)d_out;

    cudaFuncSetAttribute(tt_chain_kernel,
                         cudaFuncAttributeMaxDynamicSharedMemorySize, SMEM_BYTES);

    tt_chain_kernel<<<BATCH / TB, THREADS, SMEM_BYTES>>>(x, fc, mc, lc, out);
}

// round 5
// speedup vs baseline: 3.5102x; 1.0210x over previous
#include <cuda_runtime.h>
#include <cstdint>

// Tensor-train chain, fp32, packed-f32x2, batch-pair accumulation, 16 warps.
// Step s: t[i][r] = sum_l v[l]*C_s[l][i][r]; v'[r] = sum_i x[b][s+1][i]*t[i][r]
// 512 threads = 4 l-quarters x 4 batch-groups. Per-step 4-way vn reduction
// through lane-contiguous smem scratch (quarter 0 finalizes).

#define BATCH   4096
#define LEN     128
#define RANK    64
#define NSTEP   126
#define CSTEP   16384          // floats per mid-core step (256*64)
#define TB      32             // batches per CTA
#define THREADS 512
#define VROW    18             // float2 per v row (16 + 2 pad), 16B-aligned rows

// smem (floats): C double buffer | vbuf [64][VROW] float2 | scr 3*4*4*2*32 float2
#define SCRF2   (3*4*4*2*32)
#define SMEM_FLOATS (2*CSTEP + 64*VROW*2 + SCRF2*2)
#define SMEM_BYTES  (SMEM_FLOATS * 4)

extern __shared__ float smem_f[];

__device__ __forceinline__ uint64_t fma2(uint64_t a, uint64_t b, uint64_t c) {
    uint64_t d;
    asm("fma.rn.f32x2 %0, %1, %2, %3;" : "=l"(d) : "l"(a), "l"(b), "l"(c));
    return d;
}
__device__ __forceinline__ uint64_t mul2(uint64_t a, uint64_t b) {
    uint64_t d;
    asm("mul.rn.f32x2 %0, %1, %2;" : "=l"(d) : "l"(a), "l"(b));
    return d;
}
__device__ __forceinline__ uint64_t add2(uint64_t a, uint64_t b) {
    uint64_t d;
    asm("add.rn.f32x2 %0, %1, %2;" : "=l"(d) : "l"(a), "l"(b));
    return d;
}
__device__ __forceinline__ uint64_t dup2(float f) {
    uint64_t d;
    asm("mov.b64 %0, {%1, %1};" : "=l"(d) : "f"(f));
    return d;
}
__device__ __forceinline__ uint64_t pack2(float a, float b) {
    uint64_t d;
    asm("mov.b64 %0, {%1, %2};" : "=l"(d) : "f"(a), "f"(b));
    return d;
}
__device__ __forceinline__ float2 u2f(uint64_t a) {
    return *reinterpret_cast<float2*>(&a);
}
__device__ __forceinline__ uint32_t smem_u32(const void* p) {
    return (uint32_t)__cvta_generic_to_shared(p);
}
__device__ __forceinline__ void cp_async16(uint32_t dst, const void* src) {
    asm volatile("cp.async.cg.shared.global [%0], [%1], 16;\n" :: "r"(dst), "l"(src));
}

__global__ void __launch_bounds__(THREADS, 1)
tt_chain_kernel(const float* __restrict__ x,    // [B, 128, 4]
                const float* __restrict__ fc,   // [4, 64]
                const float* __restrict__ mc,   // [126, 64, 4, 64]
                const float* __restrict__ lc,   // [64, 4]
                float* __restrict__ out)        // [B, 1]
{
    float*  Cbuf = smem_f;                         // 2*CSTEP floats
    float2* vbuf = (float2*)(smem_f + 2*CSTEP);    // [64][VROW] batch-pair v
    float2* scr  = vbuf + 64*VROW;                 // [3][4][4][2][32] f32x2

    const int tid  = threadIdx.x;
    const int warp = tid >> 5;
    const int lane = tid & 31;
    const int q    = warp >> 2;            // l quarter: l in [16q, 16q+16)
    const int bg   = warp & 3;             // 8 batches per bg
    const int r0   = 2 * lane;             // this thread's 2 r outputs
    const int gb0  = blockIdx.x * TB + bg * 8;
    const float* xb0 = x + (size_t)gb0 * (LEN * 4);

    // ---- prefetch C[0] ----
    {
        uint32_t dst = smem_u32(Cbuf);
        #pragma unroll
        for (int j = 0; j < 8; ++j) {
            int idx = j * THREADS + tid;           // 4096 16B chunks
            cp_async16(dst + idx * 16, mc + idx * 4);
        }
        asm volatile("cp.async.commit_group;\n");
    }

    // ---- prologue: quarter 0 computes v0 pairs and stores vbuf ----
    if (q == 0) {
        #pragma unroll
        for (int p = 0; p < 4; ++p) {
            const float* xa = xb0 + (size_t)(2 * p) * (LEN * 4);
            float4 x0a = *(const float4*)xa;
            float4 x0b = *(const float4*)(xa + LEN * 4);
            #pragma unroll
            for (int j = 0; j < 2; ++j) {
                int r = r0 + j;
                float f0 = fc[r], f1 = fc[RANK + r], f2 = fc[2*RANK + r], f3 = fc[3*RANK + r];
                float va = f0*x0a.x + f1*x0a.y + f2*x0a.z + f3*x0a.w;
                float vb = f0*x0b.x + f1*x0b.y + f2*x0b.z + f3*x0b.w;
                vbuf[r * VROW + 4*bg + p] = make_float2(va, vb);
            }
        }
    }

    const int lbase = q * 16;

    // ---- main sequential chain ----
    #pragma unroll 1
    for (int s = 0; s < NSTEP; ++s) {
        // prefetch C[s+1], wait for C[s]
        if (s + 1 < NSTEP) {
            uint32_t dst = smem_u32(Cbuf + ((s + 1) & 1) * CSTEP);
            const float* src = mc + (size_t)(s + 1) * CSTEP;
            #pragma unroll
            for (int j = 0; j < 8; ++j) {
                int idx = j * THREADS + tid;
                cp_async16(dst + idx * 16, src + idx * 4);
            }
            asm volatile("cp.async.commit_group;\n");
            asm volatile("cp.async.wait_group 1;\n");
        } else {
            asm volatile("cp.async.wait_group 0;\n");
        }
        __syncthreads();   // C[s] ready; vbuf (v_s) ready; scr free

        const float*  Cs = Cbuf + (s & 1) * CSTEP;
        const float2* vb = vbuf + 4 * bg;

        uint64_t t[4][4][2];   // [i][pair][j] f32x2 over {b0,b1}

        // first l of the quarter: mul2 (initializes t)
        {
            const int l = lbase;
            const float2* vrow = vb + l * VROW;
            ulonglong2 va = *(const ulonglong2*)(vrow);
            ulonglong2 vq = *(const ulonglong2*)(vrow + 2);
            uint64_t vp[4] = { va.x, va.y, vq.x, vq.y };
            #pragma unroll
            for (int i = 0; i < 4; ++i) {
                float2 cl = *(const float2*)(Cs + (4*l + i) * RANK + r0);
                uint64_t c0 = dup2(cl.x), c1 = dup2(cl.y);
                #pragma unroll
                for (int p = 0; p < 4; ++p) {
                    t[i][p][0] = mul2(vp[p], c0);
                    t[i][p][1] = mul2(vp[p], c1);
                }
            }
        }
        // remaining 15 l values: fma2
        #pragma unroll 5
        for (int ll = 1; ll < 16; ++ll) {
            const int l = lbase + ll;
            const float2* vrow = vb + l * VROW;
            ulonglong2 va = *(const ulonglong2*)(vrow);
            ulonglong2 vq = *(const ulonglong2*)(vrow + 2);
            uint64_t vp[4] = { va.x, va.y, vq.x, vq.y };
            #pragma unroll
            for (int i = 0; i < 4; ++i) {
                float2 cl = *(const float2*)(Cs + (4*l + i) * RANK + r0);
                uint64_t c0 = dup2(cl.x), c1 = dup2(cl.y);
                #pragma unroll
                for (int p = 0; p < 4; ++p) {
                    t[i][p][0] = fma2(vp[p], c0, t[i][p][0]);
                    t[i][p][1] = fma2(vp[p], c1, t[i][p][1]);
                }
            }
        }

        // ---- combine with x[., s+1, .] : vn = sum_i xpair[i] * t[i] ----
        uint64_t vn[4][2];
        #pragma unroll
        for (int p = 0; p < 4; ++p) {
            const float* xa = xb0 + (size_t)(2 * p) * (LEN * 4) + (size_t)(s + 1) * 4;
            float4 xsa = *(const float4*)xa;
            float4 xsb = *(const float4*)(xa + LEN * 4);
            uint64_t xp0 = pack2(xsa.x, xsb.x);
            uint64_t xp1 = pack2(xsa.y, xsb.y);
            uint64_t xp2 = pack2(xsa.z, xsb.z);
            uint64_t xp3 = pack2(xsa.w, xsb.w);
            #pragma unroll
            for (int j = 0; j < 2; ++j) {
                uint64_t v = mul2(xp0, t[0][p][j]);
                v = fma2(xp1, t[1][p][j], v);
                v = fma2(xp2, t[2][p][j], v);
                v = fma2(xp3, t[3][p][j], v);
                vn[p][j] = v;
            }
        }

        // ---- 4-way reduction: quarters 1..3 write scr (lane-contiguous), q0 adds ----
        if (q != 0) {
            float2* dst = scr + (((q - 1) * 4 + bg) * 8) * 32 + lane;
            #pragma unroll
            for (int p = 0; p < 4; ++p)
                #pragma unroll
                for (int j = 0; j < 2; ++j)
                    dst[(p * 2 + j) * 32] = u2f(vn[p][j]);
        }
        __syncthreads();   // partials visible; also fences vbuf/C reads

        if (q == 0) {
            #pragma unroll
            for (int qq = 0; qq < 3; ++qq) {
                const float2* sp = scr + ((qq * 4 + bg) * 8) * 32 + lane;
                #pragma unroll
                for (int p = 0; p < 4; ++p)
                    #pragma unroll
                    for (int j = 0; j < 2; ++j) {
                        float2 f = sp[(p * 2 + j) * 32];
                        vn[p][j] = add2(vn[p][j], pack2(f.x, f.y));
                    }
            }

            if (s + 1 < NSTEP) {
                // store v_{s+1} pairs for next step
                #pragma unroll
                for (int j = 0; j < 2; ++j) {
                    float2 a = u2f(vn[0][j]), b = u2f(vn[1][j]);
                    float2 c = u2f(vn[2][j]), d = u2f(vn[3][j]);
                    float4* dst = (float4*)(vbuf + (r0 + j) * VROW + 4*bg);
                    dst[0] = make_float4(a.x, a.y, b.x, b.y);
                    dst[1] = make_float4(c.x, c.y, d.x, d.y);
                }
            } else {
                // epilogue: out[b] = sum_r v[b][r] * (sum_i lc[r][i]*x[b][127][i])
                float2 accp[4];
                #pragma unroll
                for (int p = 0; p < 4; ++p) {
                    const float* xa = xb0 + (size_t)(2 * p) * (LEN * 4) + 127 * 4;
                    float4 xe0 = *(const float4*)xa;
                    float4 xe1 = *(const float4*)(xa + LEN * 4);
                    float2 ac = make_float2(0.f, 0.f);
                    #pragma unroll
                    for (int j = 0; j < 2; ++j) {
                        int r = r0 + j;
                        float4 l4 = *(const float4*)(lc + r * 4);
                        float lv0 = l4.x*xe0.x + l4.y*xe0.y + l4.z*xe0.z + l4.w*xe0.w;
                        float lv1 = l4.x*xe1.x + l4.y*xe1.y + l4.z*xe1.z + l4.w*xe1.w;
                        float2 vv = u2f(vn[p][j]);
                        ac.x += vv.x * lv0;
                        ac.y += vv.y * lv1;
                    }
                    accp[p] = ac;
                }
                // reduce over the 32 lanes (r dimension)
                #pragma unroll
                for (int off = 16; off > 0; off >>= 1) {
                    #pragma unroll
                    for (int p = 0; p < 4; ++p) {
                        accp[p].x += __shfl_down_sync(0xffffffffu, accp[p].x, off);
                        accp[p].y += __shfl_down_sync(0xffffffffu, accp[p].y, off);
                    }
                }
                if (lane == 0) {
                    #pragma unroll
                    for (int p = 0; p < 4; ++p) {
                        out[gb0 + 2*p + 0] = accp[p].x;
                        out[gb0 + 2*p + 1] = accp[p].y;
                    }
                }
            }
        }
    }
}

extern "C" void kernel_launch(void* const* d_in, const int* in_sizes, int n_in,
                              void* d_out, int out_size) {
    const float* x  = (const float*)d_in[0];   // input_data [4096,128,4]
    const float* fc = (const float*)d_in[1];   // first_core [4,64]
    const float* mc = (const float*)d_in[2];   // mid_cores  [126,64,4,64]
    const float* lc = (const float*)d_in[3];   // last_core  [64,4]
    float* out = (float*)d_out;

    cudaFuncSetAttribute(tt_chain_kernel,
                         cudaFuncAttributeMaxDynamicSharedMemorySize, SMEM_BYTES);

    tt_chain_kernel<<<BATCH / TB, THREADS, SMEM_BYTES>>>(x, fc, mc, lc, out);
}